// round 13
// baseline (speedup 1.0000x reference)
#include <cuda_runtime.h>
#include <cuda_fp16.h>
#include <math.h>
#include <stdint.h>

#define BATCH   4
#define SEQ     2048
#define DMODEL  1024
#define NHEADS  16
#define DHEAD   64
#define MROWS   (BATCH * SEQ)         // 8192
#define NBH     (BATCH * NHEADS)      // 64
#define QSCALE  0.125f

// ---------------- scratch (static device arrays; no runtime alloc) ----------
__device__ __half d_qh2[NBH * SEQ * DHEAD];        // q (phi'd) fp16
__device__ __half d_kh2[NBH * SEQ * DHEAD];        // k (phi'd) fp16
__device__ __half d_vh2[NBH * SEQ * DHEAD];        // v fp16
__device__ float  d_gbuf[NBH * SEQ];
__device__ __half d_xh[MROWS * DMODEL];            // x in fp16
__device__ __half d_wh[4 * DMODEL * DMODEL];       // Wq,Wk,Wv,Wo in fp16
__device__ __half d_yh[MROWS * DMODEL];            // scan output y in fp16

__device__ __forceinline__ float phi(float x) {    // elu(x)+1
    return x > 0.0f ? x + 1.0f : __expf(x);
}

__device__ __forceinline__ uint32_t smem_u32(const void* p) {
    uint32_t a;
    asm("{ .reg .u64 t; cvta.to.shared.u64 t, %1; cvt.u32.u64 %0, t; }" : "=r"(a) : "l"(p));
    return a;
}

#define LDSM4(r0, r1, r2, r3, addr)                                            \
    asm volatile("ldmatrix.sync.aligned.m8n8.x4.shared.b16 {%0,%1,%2,%3}, [%4];" \
        : "=r"(r0), "=r"(r1), "=r"(r2), "=r"(r3) : "r"(addr))

#define CPA16(dst, src)                                                        \
    asm volatile("cp.async.cg.shared.global [%0], [%1], 16;" :: "r"(dst), "l"(src))

// ---------------- fp16 MMA GEMM -----------------------------------------------
// MODE 0: fused QKV, grid (24,64): C[8192,3072] = X @ [Wq;Wk;Wv]^T, epilogue
//         phi+scatter to fp16 q/k/v buffers.
// MODE 3: output projection, grid (8,64): out = Y @ Wo^T (fp32 out).
// BM=BN=128, BK=32. 128 threads = 4 warps (2x2), warp tile 64x64.
// cp.async 3-stage pipeline; smem [row][k] stride KSH=40 (conflict-free LDSM).
#define KSH     40
#define SMELEM  (128 * KSH)
#define STAGE_B (2 * SMELEM * 2)
#define GEMM_SMEM (3 * STAGE_B)             // 61440

template<int MODE>
__global__ __launch_bounds__(128, 2) void mma_gemm(const __half* __restrict__ W,
                                                   float* __restrict__ Cout) {
    const __half* A = (MODE == 3) ? d_yh : d_xh;

    extern __shared__ __half sm[];
    const uint32_t base = smem_u32(sm);

    const int tid  = threadIdx.x;
    const int bm = blockIdx.y * 128;
    const int bn = blockIdx.x * 128;
    const int wsel = bn >> 10;              // 0..2 for QKV, 0 for MODE3
    const int bnl  = bn & 1023;

    const int warp = tid >> 5;
    const int lane = tid & 31;
    const int g   = lane >> 2;
    const int tig = lane & 3;
    const int warp_m = (warp & 1) * 64;
    const int warp_n = (warp >> 1) * 64;

    const int sub = lane >> 3;
    const int r8  = lane & 7;
    const int aoff = (warp_m + (sub & 1) * 8 + r8) * KSH + (sub >> 1) * 8;
    const int boff = (warp_n + (sub >> 1) * 8 + r8) * KSH + (sub & 1) * 8;

    const __half* ga = A + (size_t)bm * DMODEL;
    const __half* gb = W + ((size_t)wsel * DMODEL + bnl) * DMODEL;

    int rowc[4], oc[4];
#pragma unroll
    for (int i = 0; i < 4; i++) {
        const int c = tid + i * 128;
        rowc[i] = c >> 2;
        oc[i]   = (c & 3) * 8;
    }

    float acc[4][8][4];
#pragma unroll
    for (int mt = 0; mt < 4; mt++)
#pragma unroll
        for (int nt = 0; nt < 8; nt++)
#pragma unroll
            for (int e = 0; e < 4; e++) acc[mt][nt][e] = 0.0f;

    auto issue = [&](int kt, int st) {
        const uint32_t sa = base + st * STAGE_B;
        const uint32_t sb = sa + SMELEM * 2;
#pragma unroll
        for (int i = 0; i < 4; i++) {
            const uint32_t d = (uint32_t)(rowc[i] * KSH + oc[i]) * 2;
            CPA16(sa + d, ga + (size_t)rowc[i] * DMODEL + kt * 32 + oc[i]);
            CPA16(sb + d, gb + (size_t)rowc[i] * DMODEL + kt * 32 + oc[i]);
        }
        asm volatile("cp.async.commit_group;" ::: "memory");
    };

    issue(0, 0);
    issue(1, 1);

    const int NT = DMODEL / 32;    // 32
    int st = 0;
    for (int kt = 0; kt < NT; kt++) {
        if (kt < NT - 2) { asm volatile("cp.async.wait_group 1;" ::: "memory"); }
        else             { asm volatile("cp.async.wait_group 0;" ::: "memory"); }
        __syncthreads();

        if (kt + 2 < NT) {
            int st2 = st + 2; if (st2 >= 3) st2 -= 3;
            issue(kt + 2, st2);
        }

        const uint32_t Ab = base + st * STAGE_B;
        const uint32_t Bb = Ab + SMELEM * 2;
#pragma unroll
        for (int k16 = 0; k16 < 32; k16 += 16) {
            unsigned af[4][4], bf[8][2];
#pragma unroll
            for (int mt = 0; mt < 4; mt++)
                LDSM4(af[mt][0], af[mt][1], af[mt][2], af[mt][3],
                      Ab + (uint32_t)(aoff + mt * 16 * KSH + k16) * 2);
#pragma unroll
            for (int p = 0; p < 4; p++)
                LDSM4(bf[2 * p][0], bf[2 * p][1], bf[2 * p + 1][0], bf[2 * p + 1][1],
                      Bb + (uint32_t)(boff + p * 16 * KSH + k16) * 2);
#pragma unroll
            for (int mt = 0; mt < 4; mt++)
#pragma unroll
                for (int nt = 0; nt < 8; nt++) {
                    asm volatile(
                        "mma.sync.aligned.m16n8k16.row.col.f32.f16.f16.f32 "
                        "{%0,%1,%2,%3}, {%4,%5,%6,%7}, {%8,%9}, {%0,%1,%2,%3};"
                        : "+f"(acc[mt][nt][0]), "+f"(acc[mt][nt][1]),
                          "+f"(acc[mt][nt][2]), "+f"(acc[mt][nt][3])
                        : "r"(af[mt][0]), "r"(af[mt][1]), "r"(af[mt][2]), "r"(af[mt][3]),
                          "r"(bf[nt][0]), "r"(bf[nt][1]));
                }
        }
        if (++st >= 3) st -= 3;
        __syncthreads();
    }

    // epilogue: paired stores (n pairs 2*tig, 2*tig+1)
#pragma unroll
    for (int mt = 0; mt < 4; mt++) {
#pragma unroll
        for (int nt = 0; nt < 8; nt++) {
#pragma unroll
            for (int ep = 0; ep < 2; ep++) {     // e pair: rows g / g+8
                const int m = bm + warp_m + mt * 16 + g + ep * 8;
                float c0 = acc[mt][nt][2 * ep + 0];
                float c1 = acc[mt][nt][2 * ep + 1];
                if (MODE == 3) {
                    const int n = bn + warp_n + nt * 8 + 2 * tig;
                    *(float2*)(Cout + (size_t)m * DMODEL + n) = make_float2(c0, c1);
                } else {
                    const int nl = bnl + warp_n + nt * 8 + 2 * tig;
                    const int b = m >> 11;
                    const int t = m & 2047;
                    const int h = nl >> 6;
                    const int d = nl & 63;
                    const size_t idx = ((size_t)(b * NHEADS + h) * SEQ + t) * DHEAD + d;
                    __half2 hv;
                    if (wsel == 0) {
                        hv = __floats2half2_rn(phi(c0 * QSCALE), phi(c1 * QSCALE));
                        *(__half2*)(d_qh2 + idx) = hv;
                    } else if (wsel == 1) {
                        hv = __floats2half2_rn(phi(c0), phi(c1));
                        *(__half2*)(d_kh2 + idx) = hv;
                    } else {
                        hv = __floats2half2_rn(c0, c1);
                        *(__half2*)(d_vh2 + idx) = hv;
                    }
                }
            }
        }
    }
}

// ---------------- prep: x->fp16 + gate (fused), weights->fp16 ---------------
__global__ __launch_bounds__(256) void prep_kernel(const float* __restrict__ x,
                                                   const float* __restrict__ wq,
                                                   const float* __restrict__ wk,
                                                   const float* __restrict__ wv,
                                                   const float* __restrict__ wo,
                                                   const float* __restrict__ Wg,
                                                   const float* __restrict__ bg) {
    const int blk = blockIdx.x;
    const int tid = threadIdx.x;
    if (blk < 1024) {
        const int w = tid >> 5, lane = tid & 31;
        const int row = blk * 8 + w;
        const float4* xr = (const float4*)(x + (size_t)row * DMODEL);
        float4 xv[8];
#pragma unroll
        for (int i = 0; i < 8; i++) xv[i] = xr[lane + i * 32];

        __half* xd = d_xh + (size_t)row * DMODEL;
#pragma unroll
        for (int i = 0; i < 8; i++) {
            __half2 h0 = __floats2half2_rn(xv[i].x, xv[i].y);
            __half2 h1 = __floats2half2_rn(xv[i].z, xv[i].w);
            uint2 u;
            u.x = *(unsigned*)&h0;
            u.y = *(unsigned*)&h1;
            *(uint2*)(xd + (lane + i * 32) * 4) = u;
        }

        const int b = row >> 11;
        const int t = row & 2047;
        for (int h = 0; h < NHEADS; h++) {
            const float4* wr = (const float4*)(Wg + (size_t)h * DMODEL);
            float acc = 0.0f;
#pragma unroll
            for (int i = 0; i < 8; i++) {
                float4 wv = wr[lane + i * 32];
                acc = fmaf(xv[i].x, wv.x, acc);
                acc = fmaf(xv[i].y, wv.y, acc);
                acc = fmaf(xv[i].z, wv.z, acc);
                acc = fmaf(xv[i].w, wv.w, acc);
            }
#pragma unroll
            for (int off = 16; off > 0; off >>= 1)
                acc += __shfl_xor_sync(0xFFFFFFFFu, acc, off);
            if (lane == 0) {
                float z = acc + bg[h];
                d_gbuf[(size_t)(b * NHEADS + h) * SEQ + t] = 1.0f / (1.0f + __expf(-z));
            }
        }
    } else {
        const int j = blk - 1024;            // 0..4095
        const int w = j >> 10;               // matrix 0..3
        const int off = ((j & 1023) << 8) + tid;
        const float* src = (w == 0) ? wq : (w == 1) ? wk : (w == 2) ? wv : wo;
        const float4 v = ((const float4*)src)[off];
        __half2 h0 = __floats2half2_rn(v.x, v.y);
        __half2 h1 = __floats2half2_rn(v.z, v.w);
        uint2 u;
        u.x = *(unsigned*)&h0;
        u.y = *(unsigned*)&h1;
        *(uint2*)(d_wh + (size_t)w * DMODEL * DMODEL + (size_t)off * 4) = u;
    }
}

// ---------------- gated scan: superstep-batched, fp16 I/O -------------------
// Block = (bh, jhalf): 32 state columns. Warp w owns rows [8w, 8w+8).
#define SS 8

__device__ __forceinline__ void h8_to_f8(uint4 u, float* f) {
    float2 a = __half22float2(*(__half2*)&u.x);
    float2 b = __half22float2(*((__half2*)&u.x + 1));
    float2 c = __half22float2(*(__half2*)&u.z);
    float2 d = __half22float2(*((__half2*)&u.z + 1));
    f[0] = a.x; f[1] = a.y; f[2] = b.x; f[3] = b.y;
    f[4] = c.x; f[5] = c.y; f[6] = d.x; f[7] = d.y;
}

__global__ __launch_bounds__(256) void scan_kernel() {
    const int blk  = blockIdx.x;           // 0..127
    const int bh   = blk >> 1;
    const int joff = (blk & 1) * 32;
    const int tid  = threadIdx.x;
    const int w    = tid >> 5;
    const int lane = tid & 31;

    __shared__ float ksh[2][SS][64];
    __shared__ float qsh[2][SS][64];
    __shared__ float vsh[2][SS][32];
    __shared__ float gsh[2][SS];
    __shared__ float ypart[SS][8][32];

    const __half* kb = d_kh2 + (size_t)bh * SEQ * DHEAD;
    const __half* qb = d_qh2 + (size_t)bh * SEQ * DHEAD;
    const __half* vb = d_vh2 + (size_t)bh * SEQ * DHEAD;
    const float*  gb = d_gbuf + (size_t)bh * SEQ;

    const int b = bh >> 4;
    const int h = bh & 15;
    __half* yout = d_yh + (size_t)(b * SEQ) * DMODEL + h * DHEAD + joff + lane;

    float S[8];
#pragma unroll
    for (int ii = 0; ii < 8; ii++) S[ii] = 0.0f;

    // load assignment:
    //  t in [0,64):    k chunk: step=t>>3, off8=(t&7)*8      (64 uint4)
    //  t in [64,128):  q chunk (t-64)
    //  t in [128,160): v chunk: j=t-128: step=j>>2, off8=(j&3)*8
    //  t in [160,168): g scalar
    const int kq_step = (tid & 63) >> 3;
    const int kq_off  = (tid & 7) * 8;
    const int v_step  = (tid - 128) >> 2;
    const int v_off   = (tid & 3) * 8;

    uint4 pkq, pv;
    float pg = 0.0f;
    if (tid < 64)        pkq = *(const uint4*)(kb + (size_t)kq_step * DHEAD + kq_off);
    else if (tid < 128)  pkq = *(const uint4*)(qb + (size_t)kq_step * DHEAD + kq_off);
    else if (tid < 160)  pv  = *(const uint4*)(vb + (size_t)v_step * DHEAD + joff + v_off);
    else if (tid < 168)  pg  = gb[tid - 160];

    int buf = 0;
    for (int t0 = 0; t0 < SEQ; t0 += SS) {
        // store prefetched data (convert fp16->fp32)
        if (tid < 64) {
            float f[8]; h8_to_f8(pkq, f);
            *(float4*)&ksh[buf][kq_step][kq_off]     = *(float4*)&f[0];
            *(float4*)&ksh[buf][kq_step][kq_off + 4] = *(float4*)&f[4];
        } else if (tid < 128) {
            float f[8]; h8_to_f8(pkq, f);
            *(float4*)&qsh[buf][kq_step][kq_off]     = *(float4*)&f[0];
            *(float4*)&qsh[buf][kq_step][kq_off + 4] = *(float4*)&f[4];
        } else if (tid < 160) {
            float f[8]; h8_to_f8(pv, f);
            *(float4*)&vsh[buf][v_step][v_off]     = *(float4*)&f[0];
            *(float4*)&vsh[buf][v_step][v_off + 4] = *(float4*)&f[4];
        } else if (tid < 168) {
            gsh[buf][tid - 160] = pg;
        }

        const int t1 = t0 + SS;
        if (t1 < SEQ) {
            if (tid < 64)        pkq = *(const uint4*)(kb + (size_t)(t1 + kq_step) * DHEAD + kq_off);
            else if (tid < 128)  pkq = *(const uint4*)(qb + (size_t)(t1 + kq_step) * DHEAD + kq_off);
            else if (tid < 160)  pv  = *(const uint4*)(vb + (size_t)(t1 + v_step) * DHEAD + joff + v_off);
            else if (tid < 168)  pg  = gb[t1 + tid - 160];
        }
        __syncthreads();

#pragma unroll
        for (int s = 0; s < SS; s++) {
            const float gt = gsh[buf][s];
            const float vj = vsh[buf][s][lane];
            const float4 k0 = *(const float4*)&ksh[buf][s][8 * w];
            const float4 k1 = *(const float4*)&ksh[buf][s][8 * w + 4];
            const float4 q0 = *(const float4*)&qsh[buf][s][8 * w];
            const float4 q1 = *(const float4*)&qsh[buf][s][8 * w + 4];
            float acc;
            S[0] = fmaf(k0.x, vj, gt * S[0]); acc = q0.x * S[0];
            S[1] = fmaf(k0.y, vj, gt * S[1]); acc = fmaf(q0.y, S[1], acc);
            S[2] = fmaf(k0.z, vj, gt * S[2]); acc = fmaf(q0.z, S[2], acc);
            S[3] = fmaf(k0.w, vj, gt * S[3]); acc = fmaf(q0.w, S[3], acc);
            S[4] = fmaf(k1.x, vj, gt * S[4]); acc = fmaf(q1.x, S[4], acc);
            S[5] = fmaf(k1.y, vj, gt * S[5]); acc = fmaf(q1.y, S[5], acc);
            S[6] = fmaf(k1.z, vj, gt * S[6]); acc = fmaf(q1.z, S[6], acc);
            S[7] = fmaf(k1.w, vj, gt * S[7]); acc = fmaf(q1.w, S[7], acc);
            ypart[s][w][lane] = acc;
        }
        __syncthreads();

        {
            const int s = tid >> 5;
            float yv = ypart[s][0][lane] + ypart[s][1][lane]
                     + ypart[s][2][lane] + ypart[s][3][lane]
                     + ypart[s][4][lane] + ypart[s][5][lane]
                     + ypart[s][6][lane] + ypart[s][7][lane];
            yout[(size_t)(t0 + s) * DMODEL] = __float2half_rn(yv);
        }
        buf ^= 1;
    }
}

// ---------------- launch ----------------------------------------------------
extern "C" void kernel_launch(void* const* d_in, const int* in_sizes, int n_in,
                              void* d_out, int out_size) {
    const float* x  = (const float*)d_in[0];
    const float* Wq = (const float*)d_in[1];
    const float* Wk = (const float*)d_in[2];
    const float* Wv = (const float*)d_in[3];
    const float* Wo = (const float*)d_in[4];
    const float* Wg = (const float*)d_in[5];
    const float* bg = (const float*)d_in[6];
    float* out = (float*)d_out;

    cudaFuncSetAttribute(mma_gemm<0>, cudaFuncAttributeMaxDynamicSharedMemorySize, GEMM_SMEM);
    cudaFuncSetAttribute(mma_gemm<3>, cudaFuncAttributeMaxDynamicSharedMemorySize, GEMM_SMEM);

    void* p = nullptr;
    cudaGetSymbolAddress(&p, d_wh);
    __half* wh_base = (__half*)p;

    prep_kernel<<<5120, 256>>>(x, Wq, Wk, Wv, Wo, Wg, bg);

    dim3 gqkv(3 * DMODEL / 128, MROWS / 128);   // (24, 64)
    mma_gemm<0><<<gqkv, 128, GEMM_SMEM>>>(wh_base, nullptr);

    scan_kernel<<<NBH * 2, 256>>>();

    dim3 go(DMODEL / 128, MROWS / 128);         // (8, 64)
    mma_gemm<3><<<go, 128, GEMM_SMEM>>>(wh_base + 3 * (size_t)DMODEL * DMODEL, out);
}

// round 14
// speedup vs baseline: 1.0508x; 1.0508x over previous
#include <cuda_runtime.h>
#include <cuda_fp16.h>
#include <math.h>
#include <stdint.h>

#define BATCH   4
#define SEQ     2048
#define DMODEL  1024
#define NHEADS  16
#define DHEAD   64
#define MROWS   (BATCH * SEQ)         // 8192
#define NBH     (BATCH * NHEADS)      // 64
#define QSCALE  0.125f

// ---------------- scratch (static device arrays; no runtime alloc) ----------
__device__ __half d_qh2[NBH * SEQ * DHEAD];        // q (phi'd) fp16
__device__ __half d_kh2[NBH * SEQ * DHEAD];        // k (phi'd) fp16
__device__ __half d_vh2[NBH * SEQ * DHEAD];        // v fp16
__device__ float  d_gbuf[NBH * SEQ];
__device__ __half d_xh[MROWS * DMODEL];            // x in fp16
__device__ __half d_wh[4 * DMODEL * DMODEL];       // Wq,Wk,Wv,Wo in fp16
__device__ __half d_yh[MROWS * DMODEL];            // scan output y in fp16

__device__ __forceinline__ float phi(float x) {    // elu(x)+1
    return x > 0.0f ? x + 1.0f : __expf(x);
}

__device__ __forceinline__ uint32_t smem_u32(const void* p) {
    uint32_t a;
    asm("{ .reg .u64 t; cvta.to.shared.u64 t, %1; cvt.u32.u64 %0, t; }" : "=r"(a) : "l"(p));
    return a;
}

#define LDSM4(r0, r1, r2, r3, addr)                                            \
    asm volatile("ldmatrix.sync.aligned.m8n8.x4.shared.b16 {%0,%1,%2,%3}, [%4];" \
        : "=r"(r0), "=r"(r1), "=r"(r2), "=r"(r3) : "r"(addr))

#define CPA16(dst, src)                                                        \
    asm volatile("cp.async.cg.shared.global [%0], [%1], 16;" :: "r"(dst), "l"(src))

// ---------------- fp16 MMA GEMM -----------------------------------------------
// MODE 0: fused QKV, grid (24,64): C[8192,3072] = X @ [Wq;Wk;Wv]^T, epilogue
//         phi+scatter to fp16 q/k/v buffers.
// MODE 3: output projection, grid (8,64): out = Y @ Wo^T (fp32 out).
// BM=BN=128, BK=32. 128 threads = 4 warps (2x2), warp tile 64x64.
// cp.async 3-stage pipeline; smem [row][k] stride KSH=40 (conflict-free LDSM).
#define KSH     40
#define SMELEM  (128 * KSH)
#define STAGE_B (2 * SMELEM * 2)
#define GEMM_SMEM (3 * STAGE_B)             // 61440

template<int MODE>
__global__ __launch_bounds__(128, 2) void mma_gemm(const __half* __restrict__ W,
                                                   float* __restrict__ Cout) {
    const __half* A = (MODE == 3) ? d_yh : d_xh;

    extern __shared__ __half sm[];
    const uint32_t base = smem_u32(sm);

    const int tid  = threadIdx.x;
    const int bm = blockIdx.y * 128;
    const int bn = blockIdx.x * 128;
    const int wsel = bn >> 10;              // 0..2 for QKV, 0 for MODE3
    const int bnl  = bn & 1023;

    const int warp = tid >> 5;
    const int lane = tid & 31;
    const int g   = lane >> 2;
    const int tig = lane & 3;
    const int warp_m = (warp & 1) * 64;
    const int warp_n = (warp >> 1) * 64;

    const int sub = lane >> 3;
    const int r8  = lane & 7;
    const int aoff = (warp_m + (sub & 1) * 8 + r8) * KSH + (sub >> 1) * 8;
    const int boff = (warp_n + (sub >> 1) * 8 + r8) * KSH + (sub & 1) * 8;

    const __half* ga = A + (size_t)bm * DMODEL;
    const __half* gb = W + ((size_t)wsel * DMODEL + bnl) * DMODEL;

    int rowc[4], oc[4];
#pragma unroll
    for (int i = 0; i < 4; i++) {
        const int c = tid + i * 128;
        rowc[i] = c >> 2;
        oc[i]   = (c & 3) * 8;
    }

    float acc[4][8][4];
#pragma unroll
    for (int mt = 0; mt < 4; mt++)
#pragma unroll
        for (int nt = 0; nt < 8; nt++)
#pragma unroll
            for (int e = 0; e < 4; e++) acc[mt][nt][e] = 0.0f;

    auto issue = [&](int kt, int st) {
        const uint32_t sa = base + st * STAGE_B;
        const uint32_t sb = sa + SMELEM * 2;
#pragma unroll
        for (int i = 0; i < 4; i++) {
            const uint32_t d = (uint32_t)(rowc[i] * KSH + oc[i]) * 2;
            CPA16(sa + d, ga + (size_t)rowc[i] * DMODEL + kt * 32 + oc[i]);
            CPA16(sb + d, gb + (size_t)rowc[i] * DMODEL + kt * 32 + oc[i]);
        }
        asm volatile("cp.async.commit_group;" ::: "memory");
    };

    issue(0, 0);
    issue(1, 1);

    const int NT = DMODEL / 32;    // 32
    int st = 0;
    for (int kt = 0; kt < NT; kt++) {
        if (kt < NT - 2) { asm volatile("cp.async.wait_group 1;" ::: "memory"); }
        else             { asm volatile("cp.async.wait_group 0;" ::: "memory"); }
        __syncthreads();

        if (kt + 2 < NT) {
            int st2 = st + 2; if (st2 >= 3) st2 -= 3;
            issue(kt + 2, st2);
        }

        const uint32_t Ab = base + st * STAGE_B;
        const uint32_t Bb = Ab + SMELEM * 2;
#pragma unroll
        for (int k16 = 0; k16 < 32; k16 += 16) {
            unsigned af[4][4], bf[8][2];
#pragma unroll
            for (int mt = 0; mt < 4; mt++)
                LDSM4(af[mt][0], af[mt][1], af[mt][2], af[mt][3],
                      Ab + (uint32_t)(aoff + mt * 16 * KSH + k16) * 2);
#pragma unroll
            for (int p = 0; p < 4; p++)
                LDSM4(bf[2 * p][0], bf[2 * p][1], bf[2 * p + 1][0], bf[2 * p + 1][1],
                      Bb + (uint32_t)(boff + p * 16 * KSH + k16) * 2);
#pragma unroll
            for (int mt = 0; mt < 4; mt++)
#pragma unroll
                for (int nt = 0; nt < 8; nt++) {
                    asm volatile(
                        "mma.sync.aligned.m16n8k16.row.col.f32.f16.f16.f32 "
                        "{%0,%1,%2,%3}, {%4,%5,%6,%7}, {%8,%9}, {%0,%1,%2,%3};"
                        : "+f"(acc[mt][nt][0]), "+f"(acc[mt][nt][1]),
                          "+f"(acc[mt][nt][2]), "+f"(acc[mt][nt][3])
                        : "r"(af[mt][0]), "r"(af[mt][1]), "r"(af[mt][2]), "r"(af[mt][3]),
                          "r"(bf[nt][0]), "r"(bf[nt][1]));
                }
        }
        if (++st >= 3) st -= 3;
        __syncthreads();
    }

    // epilogue: paired stores (n pairs 2*tig, 2*tig+1)
#pragma unroll
    for (int mt = 0; mt < 4; mt++) {
#pragma unroll
        for (int nt = 0; nt < 8; nt++) {
#pragma unroll
            for (int ep = 0; ep < 2; ep++) {     // e pair: rows g / g+8
                const int m = bm + warp_m + mt * 16 + g + ep * 8;
                float c0 = acc[mt][nt][2 * ep + 0];
                float c1 = acc[mt][nt][2 * ep + 1];
                if (MODE == 3) {
                    const int n = bn + warp_n + nt * 8 + 2 * tig;
                    *(float2*)(Cout + (size_t)m * DMODEL + n) = make_float2(c0, c1);
                } else {
                    const int nl = bnl + warp_n + nt * 8 + 2 * tig;
                    const int b = m >> 11;
                    const int t = m & 2047;
                    const int h = nl >> 6;
                    const int d = nl & 63;
                    const size_t idx = ((size_t)(b * NHEADS + h) * SEQ + t) * DHEAD + d;
                    __half2 hv;
                    if (wsel == 0) {
                        hv = __floats2half2_rn(phi(c0 * QSCALE), phi(c1 * QSCALE));
                        *(__half2*)(d_qh2 + idx) = hv;
                    } else if (wsel == 1) {
                        hv = __floats2half2_rn(phi(c0), phi(c1));
                        *(__half2*)(d_kh2 + idx) = hv;
                    } else {
                        hv = __floats2half2_rn(c0, c1);
                        *(__half2*)(d_vh2 + idx) = hv;
                    }
                }
            }
        }
    }
}

// ---------------- prep: x->fp16 + gate (fused), weights->fp16 ---------------
__global__ __launch_bounds__(256) void prep_kernel(const float* __restrict__ x,
                                                   const float* __restrict__ wq,
                                                   const float* __restrict__ wk,
                                                   const float* __restrict__ wv,
                                                   const float* __restrict__ wo,
                                                   const float* __restrict__ Wg,
                                                   const float* __restrict__ bg) {
    const int blk = blockIdx.x;
    const int tid = threadIdx.x;
    if (blk < 1024) {
        const int w = tid >> 5, lane = tid & 31;
        const int row = blk * 8 + w;
        const float4* xr = (const float4*)(x + (size_t)row * DMODEL);
        float4 xv[8];
#pragma unroll
        for (int i = 0; i < 8; i++) xv[i] = xr[lane + i * 32];

        __half* xd = d_xh + (size_t)row * DMODEL;
#pragma unroll
        for (int i = 0; i < 8; i++) {
            __half2 h0 = __floats2half2_rn(xv[i].x, xv[i].y);
            __half2 h1 = __floats2half2_rn(xv[i].z, xv[i].w);
            uint2 u;
            u.x = *(unsigned*)&h0;
            u.y = *(unsigned*)&h1;
            *(uint2*)(xd + (lane + i * 32) * 4) = u;
        }

        const int b = row >> 11;
        const int t = row & 2047;
        for (int h = 0; h < NHEADS; h++) {
            const float4* wr = (const float4*)(Wg + (size_t)h * DMODEL);
            float acc = 0.0f;
#pragma unroll
            for (int i = 0; i < 8; i++) {
                float4 wv = wr[lane + i * 32];
                acc = fmaf(xv[i].x, wv.x, acc);
                acc = fmaf(xv[i].y, wv.y, acc);
                acc = fmaf(xv[i].z, wv.z, acc);
                acc = fmaf(xv[i].w, wv.w, acc);
            }
#pragma unroll
            for (int off = 16; off > 0; off >>= 1)
                acc += __shfl_xor_sync(0xFFFFFFFFu, acc, off);
            if (lane == 0) {
                float z = acc + bg[h];
                d_gbuf[(size_t)(b * NHEADS + h) * SEQ + t] = 1.0f / (1.0f + __expf(-z));
            }
        }
    } else {
        const int j = blk - 1024;            // 0..4095
        const int w = j >> 10;               // matrix 0..3
        const int off = ((j & 1023) << 8) + tid;
        const float* src = (w == 0) ? wq : (w == 1) ? wk : (w == 2) ? wv : wo;
        const float4 v = ((const float4*)src)[off];
        __half2 h0 = __floats2half2_rn(v.x, v.y);
        __half2 h1 = __floats2half2_rn(v.z, v.w);
        uint2 u;
        u.x = *(unsigned*)&h0;
        u.y = *(unsigned*)&h1;
        *(uint2*)(d_wh + (size_t)w * DMODEL * DMODEL + (size_t)off * 4) = u;
    }
}

// ---------------- gated scan: cp.async pipelined supersteps -----------------
// Block = (bh, jhalf): 32 state columns. Warp w owns rows [8w, 8w+8).
// 4 smem buffers, 3 supersteps (24 steps) of prefetch in flight via cp.async.
#define SS   8
#define NBUF 4
#define NSS  (SEQ / SS)            // 256 supersteps

__device__ __forceinline__ void h8_to_f8(uint4 u, float* f) {
    float2 a = __half22float2(*(__half2*)&u.x);
    float2 b = __half22float2(*((__half2*)&u.x + 1));
    float2 c = __half22float2(*(__half2*)&u.z);
    float2 d = __half22float2(*((__half2*)&u.z + 1));
    f[0] = a.x; f[1] = a.y; f[2] = b.x; f[3] = b.y;
    f[4] = c.x; f[5] = c.y; f[6] = d.x; f[7] = d.y;
}

__global__ __launch_bounds__(256) void scan_kernel() {
    const int blk  = blockIdx.x;           // 0..127
    const int bh   = blk >> 1;
    const int joff = (blk & 1) * 32;
    const int tid  = threadIdx.x;
    const int w    = tid >> 5;
    const int lane = tid & 31;

    __shared__ __half ksh[NBUF][SS][64];   // 4 KB
    __shared__ __half qsh[NBUF][SS][64];   // 4 KB
    __shared__ __half vsh[NBUF][SS][32];   // 2 KB
    __shared__ float  gsh[NBUF][SS];       // 128 B
    __shared__ float  ypart[SS][8][32];    // 4 KB

    const __half* kb = d_kh2 + (size_t)bh * SEQ * DHEAD;
    const __half* qb = d_qh2 + (size_t)bh * SEQ * DHEAD;
    const __half* vb = d_vh2 + (size_t)bh * SEQ * DHEAD;
    const float*  gb = d_gbuf + (size_t)bh * SEQ;

    const int b = bh >> 4;
    const int h = bh & 15;
    __half* yout = d_yh + (size_t)(b * SEQ) * DMODEL + h * DHEAD + joff + lane;

    const uint32_t k_s = smem_u32(&ksh[0][0][0]);
    const uint32_t q_s = smem_u32(&qsh[0][0][0]);
    const uint32_t v_s = smem_u32(&vsh[0][0][0]);
    const uint32_t g_s = smem_u32(&gsh[0][0]);

    float S[8];
#pragma unroll
    for (int ii = 0; ii < 8; ii++) S[ii] = 0.0f;

    // cp.async assignment (every thread commits every issue call):
    //  tid [0,64):    k  — step=tid>>3,      chunk=tid&7 (16B)
    //  tid [64,128):  q  — step=(tid-64)>>3, chunk=(tid-64)&7
    //  tid [128,160): v  — step=(tid-128)>>2, chunk=(tid-128)&3
    //  tid [160,162): g  — 16B of floats each
    auto issue = [&](int t1, int buf) {
        if (tid < 64) {
            const int step = tid >> 3, c = tid & 7;
            CPA16(k_s + (uint32_t)(((buf * SS + step) * 64 + c * 8) * 2),
                  kb + (size_t)(t1 + step) * DHEAD + c * 8);
        } else if (tid < 128) {
            const int t2 = tid - 64;
            const int step = t2 >> 3, c = t2 & 7;
            CPA16(q_s + (uint32_t)(((buf * SS + step) * 64 + c * 8) * 2),
                  qb + (size_t)(t1 + step) * DHEAD + c * 8);
        } else if (tid < 160) {
            const int t3 = tid - 128;
            const int step = t3 >> 2, c = t3 & 3;
            CPA16(v_s + (uint32_t)(((buf * SS + step) * 32 + c * 8) * 2),
                  vb + (size_t)(t1 + step) * DHEAD + joff + c * 8);
        } else if (tid < 162) {
            const int s0 = (tid - 160) * 4;
            CPA16(g_s + (uint32_t)((buf * SS + s0) * 4), gb + t1 + s0);
        }
        asm volatile("cp.async.commit_group;" ::: "memory");
    };

    issue(0 * SS, 0);
    issue(1 * SS, 1);
    issue(2 * SS, 2);

    for (int ss = 0; ss < NSS; ss++) {
        const int buf = ss & 3;
        if (ss < NSS - 2) { asm volatile("cp.async.wait_group 2;" ::: "memory"); }
        else              { asm volatile("cp.async.wait_group 0;" ::: "memory"); }
        __syncthreads();   // buf data visible; all threads done with ss-1

        if (ss + 3 < NSS) issue((ss + 3) * SS, (ss + 3) & 3);

#pragma unroll
        for (int s = 0; s < SS; s++) {
            const float gt = gsh[buf][s];
            const uint4 ku = *(const uint4*)&ksh[buf][s][8 * w];
            const uint4 qu = *(const uint4*)&qsh[buf][s][8 * w];
            float kf[8], qf[8];
            h8_to_f8(ku, kf);
            h8_to_f8(qu, qf);
            const float vj = __half2float(vsh[buf][s][lane]);
            float acc;
            S[0] = fmaf(kf[0], vj, gt * S[0]); acc = qf[0] * S[0];
            S[1] = fmaf(kf[1], vj, gt * S[1]); acc = fmaf(qf[1], S[1], acc);
            S[2] = fmaf(kf[2], vj, gt * S[2]); acc = fmaf(qf[2], S[2], acc);
            S[3] = fmaf(kf[3], vj, gt * S[3]); acc = fmaf(qf[3], S[3], acc);
            S[4] = fmaf(kf[4], vj, gt * S[4]); acc = fmaf(qf[4], S[4], acc);
            S[5] = fmaf(kf[5], vj, gt * S[5]); acc = fmaf(qf[5], S[5], acc);
            S[6] = fmaf(kf[6], vj, gt * S[6]); acc = fmaf(qf[6], S[6], acc);
            S[7] = fmaf(kf[7], vj, gt * S[7]); acc = fmaf(qf[7], S[7], acc);
            ypart[s][w][lane] = acc;
        }
        __syncthreads();   // ypart complete

        {
            const int s = tid >> 5;
            float yv = ypart[s][0][lane] + ypart[s][1][lane]
                     + ypart[s][2][lane] + ypart[s][3][lane]
                     + ypart[s][4][lane] + ypart[s][5][lane]
                     + ypart[s][6][lane] + ypart[s][7][lane];
            yout[(size_t)(ss * SS + s) * DMODEL] = __float2half_rn(yv);
        }
    }
}

// ---------------- launch ----------------------------------------------------
extern "C" void kernel_launch(void* const* d_in, const int* in_sizes, int n_in,
                              void* d_out, int out_size) {
    const float* x  = (const float*)d_in[0];
    const float* Wq = (const float*)d_in[1];
    const float* Wk = (const float*)d_in[2];
    const float* Wv = (const float*)d_in[3];
    const float* Wo = (const float*)d_in[4];
    const float* Wg = (const float*)d_in[5];
    const float* bg = (const float*)d_in[6];
    float* out = (float*)d_out;

    cudaFuncSetAttribute(mma_gemm<0>, cudaFuncAttributeMaxDynamicSharedMemorySize, GEMM_SMEM);
    cudaFuncSetAttribute(mma_gemm<3>, cudaFuncAttributeMaxDynamicSharedMemorySize, GEMM_SMEM);

    void* p = nullptr;
    cudaGetSymbolAddress(&p, d_wh);
    __half* wh_base = (__half*)p;

    prep_kernel<<<5120, 256>>>(x, Wq, Wk, Wv, Wo, Wg, bg);

    dim3 gqkv(3 * DMODEL / 128, MROWS / 128);   // (24, 64)
    mma_gemm<0><<<gqkv, 128, GEMM_SMEM>>>(wh_base, nullptr);

    scan_kernel<<<NBH * 2, 256>>>();

    dim3 go(DMODEL / 128, MROWS / 128);         // (8, 64)
    mma_gemm<3><<<go, 128, GEMM_SMEM>>>(wh_base + 3 * (size_t)DMODEL * DMODEL, out);
}

// round 16
// speedup vs baseline: 1.1030x; 1.0497x over previous
#include <cuda_runtime.h>
#include <cuda_fp16.h>
#include <math.h>
#include <stdint.h>

#define BATCH   4
#define SEQ     2048
#define DMODEL  1024
#define NHEADS  16
#define DHEAD   64
#define MROWS   (BATCH * SEQ)         // 8192
#define NBH     (BATCH * NHEADS)      // 64
#define QSCALE  0.125f

// ---------------- scratch (static device arrays; no runtime alloc) ----------
__device__ __half d_qh2[NBH * SEQ * DHEAD];        // q (phi'd) fp16
__device__ __half d_kh2[NBH * SEQ * DHEAD];        // k (phi'd) fp16
__device__ __half d_vh2[NBH * SEQ * DHEAD];        // v fp16
__device__ float  d_gbuf[NBH * SEQ];
__device__ __half d_xh[MROWS * DMODEL];            // x in fp16
// slots: 0=Wq 1=Wk 2=Wv 3=gate-pad(128 rows used) 4=Wo
__device__ __half d_wh[5 * DMODEL * DMODEL];
__device__ __half d_yh[MROWS * DMODEL];            // scan output y in fp16

__device__ __forceinline__ float phi(float x) {    // elu(x)+1
    return x > 0.0f ? x + 1.0f : __expf(x);
}

__device__ __forceinline__ uint32_t smem_u32(const void* p) {
    uint32_t a;
    asm("{ .reg .u64 t; cvta.to.shared.u64 t, %1; cvt.u32.u64 %0, t; }" : "=r"(a) : "l"(p));
    return a;
}

#define LDSM4(r0, r1, r2, r3, addr)                                            \
    asm volatile("ldmatrix.sync.aligned.m8n8.x4.shared.b16 {%0,%1,%2,%3}, [%4];" \
        : "=r"(r0), "=r"(r1), "=r"(r2), "=r"(r3) : "r"(addr))

#define CPA16(dst, src)                                                        \
    asm volatile("cp.async.cg.shared.global [%0], [%1], 16;" :: "r"(dst), "l"(src))

// ---------------- fp16 MMA GEMM -----------------------------------------------
// MODE 0: fused QKV+gate, grid (25,64): C[8192,3200] = X @ [Wq;Wk;Wv;Wgpad]^T,
//         epilogue: phi+scatter q/k/v fp16; sigmoid(c+bg) -> d_gbuf (tile 24).
// MODE 3: output projection, grid (8,64): out = Y @ Wo^T (fp32 out).
// BM=BN=128, BK=32. 128 threads = 4 warps (2x2), warp tile 64x64.
// cp.async 3-stage pipeline; smem [row][k] stride KSH=40 (conflict-free LDSM).
#define KSH     40
#define SMELEM  (128 * KSH)
#define STAGE_B (2 * SMELEM * 2)
#define GEMM_SMEM (3 * STAGE_B)             // 61440

template<int MODE>
__global__ __launch_bounds__(128, 2) void mma_gemm(const __half* __restrict__ W,
                                                   float* __restrict__ Cout,
                                                   const float* __restrict__ bgp) {
    const __half* A = (MODE == 3) ? d_yh : d_xh;

    extern __shared__ __half sm[];
    const uint32_t base = smem_u32(sm);

    const int tid  = threadIdx.x;
    const int bm = blockIdx.y * 128;
    const int bn = blockIdx.x * 128;
    const int wsel = bn >> 10;              // 0..3 for QKV+gate, 0 for MODE3
    const int bnl  = bn & 1023;

    const int warp = tid >> 5;
    const int lane = tid & 31;
    const int g   = lane >> 2;
    const int tig = lane & 3;
    const int warp_m = (warp & 1) * 64;
    const int warp_n = (warp >> 1) * 64;

    const int sub = lane >> 3;
    const int r8  = lane & 7;
    const int aoff = (warp_m + (sub & 1) * 8 + r8) * KSH + (sub >> 1) * 8;
    const int boff = (warp_n + (sub >> 1) * 8 + r8) * KSH + (sub & 1) * 8;

    const __half* ga = A + (size_t)bm * DMODEL;
    const __half* gb = W + ((size_t)wsel * DMODEL + bnl) * DMODEL;

    int rowc[4], oc[4];
#pragma unroll
    for (int i = 0; i < 4; i++) {
        const int c = tid + i * 128;
        rowc[i] = c >> 2;
        oc[i]   = (c & 3) * 8;
    }

    float acc[4][8][4];
#pragma unroll
    for (int mt = 0; mt < 4; mt++)
#pragma unroll
        for (int nt = 0; nt < 8; nt++)
#pragma unroll
            for (int e = 0; e < 4; e++) acc[mt][nt][e] = 0.0f;

    auto issue = [&](int kt, int st) {
        const uint32_t sa = base + st * STAGE_B;
        const uint32_t sb = sa + SMELEM * 2;
#pragma unroll
        for (int i = 0; i < 4; i++) {
            const uint32_t d = (uint32_t)(rowc[i] * KSH + oc[i]) * 2;
            CPA16(sa + d, ga + (size_t)rowc[i] * DMODEL + kt * 32 + oc[i]);
            CPA16(sb + d, gb + (size_t)rowc[i] * DMODEL + kt * 32 + oc[i]);
        }
        asm volatile("cp.async.commit_group;" ::: "memory");
    };

    issue(0, 0);
    issue(1, 1);

    const int NT = DMODEL / 32;    // 32
    int st = 0;
    for (int kt = 0; kt < NT; kt++) {
        if (kt < NT - 2) { asm volatile("cp.async.wait_group 1;" ::: "memory"); }
        else             { asm volatile("cp.async.wait_group 0;" ::: "memory"); }
        __syncthreads();

        if (kt + 2 < NT) {
            int st2 = st + 2; if (st2 >= 3) st2 -= 3;
            issue(kt + 2, st2);
        }

        const uint32_t Ab = base + st * STAGE_B;
        const uint32_t Bb = Ab + SMELEM * 2;
#pragma unroll
        for (int k16 = 0; k16 < 32; k16 += 16) {
            unsigned af[4][4], bf[8][2];
#pragma unroll
            for (int mt = 0; mt < 4; mt++)
                LDSM4(af[mt][0], af[mt][1], af[mt][2], af[mt][3],
                      Ab + (uint32_t)(aoff + mt * 16 * KSH + k16) * 2);
#pragma unroll
            for (int p = 0; p < 4; p++)
                LDSM4(bf[2 * p][0], bf[2 * p][1], bf[2 * p + 1][0], bf[2 * p + 1][1],
                      Bb + (uint32_t)(boff + p * 16 * KSH + k16) * 2);
#pragma unroll
            for (int mt = 0; mt < 4; mt++)
#pragma unroll
                for (int nt = 0; nt < 8; nt++) {
                    asm volatile(
                        "mma.sync.aligned.m16n8k16.row.col.f32.f16.f16.f32 "
                        "{%0,%1,%2,%3}, {%4,%5,%6,%7}, {%8,%9}, {%0,%1,%2,%3};"
                        : "+f"(acc[mt][nt][0]), "+f"(acc[mt][nt][1]),
                          "+f"(acc[mt][nt][2]), "+f"(acc[mt][nt][3])
                        : "r"(af[mt][0]), "r"(af[mt][1]), "r"(af[mt][2]), "r"(af[mt][3]),
                          "r"(bf[nt][0]), "r"(bf[nt][1]));
                }
        }
        if (++st >= 3) st -= 3;
        __syncthreads();
    }

    // epilogue: paired stores (n pairs 2*tig, 2*tig+1)
#pragma unroll
    for (int mt = 0; mt < 4; mt++) {
#pragma unroll
        for (int nt = 0; nt < 8; nt++) {
#pragma unroll
            for (int ep = 0; ep < 2; ep++) {     // e pair: rows g / g+8
                const int m = bm + warp_m + mt * 16 + g + ep * 8;
                float c0 = acc[mt][nt][2 * ep + 0];
                float c1 = acc[mt][nt][2 * ep + 1];
                if (MODE == 3) {
                    const int n = bn + warp_n + nt * 8 + 2 * tig;
                    *(float2*)(Cout + (size_t)m * DMODEL + n) = make_float2(c0, c1);
                } else {
                    const int nl = bnl + warp_n + nt * 8 + 2 * tig;
                    const int b = m >> 11;
                    const int t = m & 2047;
                    if (wsel == 3) {
                        if (nl < NHEADS) {     // gate columns
                            float g0 = 1.0f / (1.0f + __expf(-(c0 + bgp[nl])));
                            float g1 = 1.0f / (1.0f + __expf(-(c1 + bgp[nl + 1])));
                            d_gbuf[(size_t)(b * NHEADS + nl) * SEQ + t]     = g0;
                            d_gbuf[(size_t)(b * NHEADS + nl + 1) * SEQ + t] = g1;
                        }
                    } else {
                        const int h = nl >> 6;
                        const int d = nl & 63;
                        const size_t idx = ((size_t)(b * NHEADS + h) * SEQ + t) * DHEAD + d;
                        __half2 hv;
                        if (wsel == 0) {
                            hv = __floats2half2_rn(phi(c0 * QSCALE), phi(c1 * QSCALE));
                            *(__half2*)(d_qh2 + idx) = hv;
                        } else if (wsel == 1) {
                            hv = __floats2half2_rn(phi(c0), phi(c1));
                            *(__half2*)(d_kh2 + idx) = hv;
                        } else {
                            hv = __floats2half2_rn(c0, c1);
                            *(__half2*)(d_vh2 + idx) = hv;
                        }
                    }
                }
            }
        }
    }
}

// ---------------- prep: pure streaming fp32->fp16 conversions ----------------
// blocks [0,8192):        x  (1 float4 per thread)
// blocks [8192,12288):    Wq,Wk,Wv,Wo -> slots 0,1,2,4
// blocks [12288,12352):   gate slot 3: rows 0-15 = Wg, rows 16-127 = 0
#define XB 8192
#define WB 4096
#define GB 64
#define NW4 (DMODEL * DMODEL / 4)

__global__ __launch_bounds__(256) void prep_kernel(const float* __restrict__ x,
                                                   const float* __restrict__ wq,
                                                   const float* __restrict__ wk,
                                                   const float* __restrict__ wv,
                                                   const float* __restrict__ wo,
                                                   const float* __restrict__ Wg) {
    const int blk = blockIdx.x;
    const int tid = threadIdx.x;
    if (blk < XB) {
        const int i = blk * 256 + tid;
        const float4 v = ((const float4*)x)[i];
        __half2 h0 = __floats2half2_rn(v.x, v.y);
        __half2 h1 = __floats2half2_rn(v.z, v.w);
        uint2 u;
        u.x = *(unsigned*)&h0;
        u.y = *(unsigned*)&h1;
        *(uint2*)(d_xh + (size_t)i * 4) = u;
    } else if (blk < XB + WB) {
        const int j = blk - XB;
        const int w = j >> 10;
        const int slot = (w == 3) ? 4 : w;
        const int off = ((j & 1023) << 8) + tid;
        const float* src = (w == 0) ? wq : (w == 1) ? wk : (w == 2) ? wv : wo;
        const float4 v = ((const float4*)src)[off];
        __half2 h0 = __floats2half2_rn(v.x, v.y);
        __half2 h1 = __floats2half2_rn(v.z, v.w);
        uint2 u;
        u.x = *(unsigned*)&h0;
        u.y = *(unsigned*)&h1;
        *(uint2*)(d_wh + (size_t)slot * DMODEL * DMODEL + (size_t)off * 4) = u;
    } else {
        const int idx = (blk - XB - WB) * 256 + tid;   // 0..16383
        const int halfoff = idx * 8;
        const int row = halfoff >> 10;
        const int col = halfoff & 1023;
        __half2 h[4];
        if (row < NHEADS) {
            const float4 v0 = *(const float4*)(Wg + (size_t)row * DMODEL + col);
            const float4 v1 = *(const float4*)(Wg + (size_t)row * DMODEL + col + 4);
            h[0] = __floats2half2_rn(v0.x, v0.y);
            h[1] = __floats2half2_rn(v0.z, v0.w);
            h[2] = __floats2half2_rn(v1.x, v1.y);
            h[3] = __floats2half2_rn(v1.z, v1.w);
        } else {
            h[0] = h[1] = h[2] = h[3] = __floats2half2_rn(0.0f, 0.0f);
        }
        uint4 u;
        u.x = *(unsigned*)&h[0];
        u.y = *(unsigned*)&h[1];
        u.z = *(unsigned*)&h[2];
        u.w = *(unsigned*)&h[3];
        *(uint4*)(d_wh + (size_t)3 * DMODEL * DMODEL + halfoff) = u;
    }
}

// ---------------- gated scan: cp.async pipeline + warp-local f32 staging ----
// Block = (bh, jhalf): 32 state columns. Warp w owns rows [8w, 8w+8).
#define SS   8
#define NBUF 4
#define NSS  (SEQ / SS)            // 256 supersteps

__global__ __launch_bounds__(256) void scan_kernel() {
    const int blk  = blockIdx.x;           // 0..127
    const int bh   = blk >> 1;
    const int joff = (blk & 1) * 32;
    const int tid  = threadIdx.x;
    const int w    = tid >> 5;
    const int lane = tid & 31;

    __shared__ __half ksh[NBUF][SS][64];   // 4 KB
    __shared__ __half qsh[NBUF][SS][64];   // 4 KB
    __shared__ __half vsh[NBUF][SS][32];   // 2 KB
    __shared__ float  gsh[NBUF][SS];       // 128 B
    __shared__ float  kst[8][SS][8];       // 2 KB warp-private fp32 staging
    __shared__ float  qst[8][SS][8];       // 2 KB
    __shared__ float  ypart[SS][8][32];    // 4 KB

    const __half* kb = d_kh2 + (size_t)bh * SEQ * DHEAD;
    const __half* qb = d_qh2 + (size_t)bh * SEQ * DHEAD;
    const __half* vb = d_vh2 + (size_t)bh * SEQ * DHEAD;
    const float*  gb = d_gbuf + (size_t)bh * SEQ;

    const int b = bh >> 4;
    const int h = bh & 15;
    __half* yout = d_yh + (size_t)(b * SEQ) * DMODEL + h * DHEAD + joff + lane;

    const uint32_t k_s = smem_u32(&ksh[0][0][0]);
    const uint32_t q_s = smem_u32(&qsh[0][0][0]);
    const uint32_t v_s = smem_u32(&vsh[0][0][0]);
    const uint32_t g_s = smem_u32(&gsh[0][0]);

    float S[8];
#pragma unroll
    for (int ii = 0; ii < 8; ii++) S[ii] = 0.0f;

    // cp.async assignment (every thread commits every issue call)
    auto issue = [&](int t1, int buf) {
        if (tid < 64) {
            const int step = tid >> 3, c = tid & 7;
            CPA16(k_s + (uint32_t)(((buf * SS + step) * 64 + c * 8) * 2),
                  kb + (size_t)(t1 + step) * DHEAD + c * 8);
        } else if (tid < 128) {
            const int t2 = tid - 64;
            const int step = t2 >> 3, c = t2 & 7;
            CPA16(q_s + (uint32_t)(((buf * SS + step) * 64 + c * 8) * 2),
                  qb + (size_t)(t1 + step) * DHEAD + c * 8);
        } else if (tid < 160) {
            const int t3 = tid - 128;
            const int step = t3 >> 2, c = t3 & 3;
            CPA16(v_s + (uint32_t)(((buf * SS + step) * 32 + c * 8) * 2),
                  vb + (size_t)(t1 + step) * DHEAD + joff + c * 8);
        } else if (tid < 162) {
            const int s0 = (tid - 160) * 4;
            CPA16(g_s + (uint32_t)((buf * SS + s0) * 4), gb + t1 + s0);
        }
        asm volatile("cp.async.commit_group;" ::: "memory");
    };

    issue(0 * SS, 0);
    issue(1 * SS, 1);
    issue(2 * SS, 2);

    for (int ss = 0; ss < NSS; ss++) {
        const int buf = ss & 3;
        if (ss < NSS - 2) { asm volatile("cp.async.wait_group 2;" ::: "memory"); }
        else              { asm volatile("cp.async.wait_group 0;" ::: "memory"); }
        __syncthreads();   // buf data visible; all threads done with ss-1

        if (ss + 3 < NSS) issue((ss + 3) * SS, (ss + 3) & 3);

        // warp-local fp16 -> fp32 pre-convert of this warp's k/q rows:
        // lane handles half2 element (s = lane>>2, p = lane&3) of rows 8w..8w+8
        {
            const __half2* kh2 = (const __half2*)&ksh[buf][0][0];  // [SS][32]
            const __half2* qh2 = (const __half2*)&qsh[buf][0][0];
            const int s = lane >> 2, p = lane & 3;
            const int src = s * 32 + 4 * w + p;
            float2 kf = __half22float2(kh2[src]);
            float2 qf = __half22float2(qh2[src]);
            *(float2*)&kst[w][s][2 * p] = kf;
            *(float2*)&qst[w][s][2 * p] = qf;
            __syncwarp();
        }

#pragma unroll
        for (int s = 0; s < SS; s++) {
            const float gt = gsh[buf][s];
            const float4 k0 = *(const float4*)&kst[w][s][0];
            const float4 k1 = *(const float4*)&kst[w][s][4];
            const float4 q0 = *(const float4*)&qst[w][s][0];
            const float4 q1 = *(const float4*)&qst[w][s][4];
            const float vj = __half2float(vsh[buf][s][lane]);
            float acc;
            S[0] = fmaf(k0.x, vj, gt * S[0]); acc = q0.x * S[0];
            S[1] = fmaf(k0.y, vj, gt * S[1]); acc = fmaf(q0.y, S[1], acc);
            S[2] = fmaf(k0.z, vj, gt * S[2]); acc = fmaf(q0.z, S[2], acc);
            S[3] = fmaf(k0.w, vj, gt * S[3]); acc = fmaf(q0.w, S[3], acc);
            S[4] = fmaf(k1.x, vj, gt * S[4]); acc = fmaf(q1.x, S[4], acc);
            S[5] = fmaf(k1.y, vj, gt * S[5]); acc = fmaf(q1.y, S[5], acc);
            S[6] = fmaf(k1.z, vj, gt * S[6]); acc = fmaf(q1.z, S[6], acc);
            S[7] = fmaf(k1.w, vj, gt * S[7]); acc = fmaf(q1.w, S[7], acc);
            ypart[s][w][lane] = acc;
        }
        __syncthreads();   // ypart complete

        {
            const int s = tid >> 5;
            float yv = ypart[s][0][lane] + ypart[s][1][lane]
                     + ypart[s][2][lane] + ypart[s][3][lane]
                     + ypart[s][4][lane] + ypart[s][5][lane]
                     + ypart[s][6][lane] + ypart[s][7][lane];
            yout[(size_t)(ss * SS + s) * DMODEL] = __float2half_rn(yv);
        }
    }
}

// ---------------- launch ----------------------------------------------------
extern "C" void kernel_launch(void* const* d_in, const int* in_sizes, int n_in,
                              void* d_out, int out_size) {
    const float* x  = (const float*)d_in[0];
    const float* Wq = (const float*)d_in[1];
    const float* Wk = (const float*)d_in[2];
    const float* Wv = (const float*)d_in[3];
    const float* Wo = (const float*)d_in[4];
    const float* Wg = (const float*)d_in[5];
    const float* bg = (const float*)d_in[6];
    float* out = (float*)d_out;

    cudaFuncSetAttribute(mma_gemm<0>, cudaFuncAttributeMaxDynamicSharedMemorySize, GEMM_SMEM);
    cudaFuncSetAttribute(mma_gemm<3>, cudaFuncAttributeMaxDynamicSharedMemorySize, GEMM_SMEM);

    void* p = nullptr;
    cudaGetSymbolAddress(&p, d_wh);
    __half* wh_base = (__half*)p;

    prep_kernel<<<XB + WB + GB, 256>>>(x, Wq, Wk, Wv, Wo, Wg);

    dim3 gqkv(25, MROWS / 128);                 // (25, 64): QKV + gate tile
    mma_gemm<0><<<gqkv, 128, GEMM_SMEM>>>(wh_base, nullptr, bg);

    scan_kernel<<<NBH * 2, 256>>>();

    dim3 go(DMODEL / 128, MROWS / 128);         // (8, 64)
    mma_gemm<3><<<go, 128, GEMM_SMEM>>>(wh_base + 4 * (size_t)DMODEL * DMODEL, out, nullptr);
}

// round 17
// speedup vs baseline: 1.1949x; 1.0834x over previous
#include <cuda_runtime.h>
#include <cuda_fp16.h>
#include <math.h>
#include <stdint.h>

#define BATCH   4
#define SEQ     2048
#define DMODEL  1024
#define NHEADS  16
#define DHEAD   64
#define MROWS   (BATCH * SEQ)         // 8192
#define NBH     (BATCH * NHEADS)      // 64
#define QSCALE  0.125f

// ---------------- scratch (static device arrays; no runtime alloc) ----------
__device__ __half d_qh2[NBH * SEQ * DHEAD];        // q (phi'd) fp16
__device__ __half d_kh2[NBH * SEQ * DHEAD];        // k (phi'd) fp16
__device__ __half d_vh2[NBH * SEQ * DHEAD];        // v fp16
__device__ float  d_gbuf[NBH * SEQ];
__device__ __half d_xh[MROWS * DMODEL];            // x in fp16
// slots: 0=Wq 1=Wk 2=Wv 3=gate-pad(16 rows used) 4=Wo
__device__ __half d_wh[5 * DMODEL * DMODEL];
__device__ __half d_yh[MROWS * DMODEL];            // scan output y in fp16

__device__ __forceinline__ float phi(float x) {    // elu(x)+1
    return x > 0.0f ? x + 1.0f : __expf(x);
}

__device__ __forceinline__ uint32_t smem_u32(const void* p) {
    uint32_t a;
    asm("{ .reg .u64 t; cvta.to.shared.u64 t, %1; cvt.u32.u64 %0, t; }" : "=r"(a) : "l"(p));
    return a;
}

#define LDSM4(r0, r1, r2, r3, addr)                                            \
    asm volatile("ldmatrix.sync.aligned.m8n8.x4.shared.b16 {%0,%1,%2,%3}, [%4];" \
        : "=r"(r0), "=r"(r1), "=r"(r2), "=r"(r3) : "r"(addr))

#define CPA16(dst, src)                                                        \
    asm volatile("cp.async.cg.shared.global [%0], [%1], 16;" :: "r"(dst), "l"(src))

// ---------------- fp16 MMA GEMM -----------------------------------------------
// MODE 0: fused QKV+gate, grid (25,64): C[8192,3200] = X @ [Wq;Wk;Wv;Wgpad]^T.
// MODE 3: output projection, grid (8,64): out = Y @ Wo^T (fp32 out).
// BM=BN=128, BK=64 halves (128B rows). 128 threads = 4 warps (2x2), warp tile
// 64x64. XOR-swizzled smem (col16 ^ (row&7)) -> conflict-free ldmatrix, no pad.
// cp.async 3-stage pipeline, ONE barrier per k-tile (16 k-tiles).
#define BKH     64                          // k halves per tile
#define TILEB   (128 * 128)                 // bytes per matrix tile
#define STAGE_B (2 * TILEB)                 // 32 KB (A + B)
#define NSTG    3
#define GEMM_SMEM (NSTG * STAGE_B)          // 98304

template<int MODE>
__global__ __launch_bounds__(128, 2) void mma_gemm(const __half* __restrict__ W,
                                                   float* __restrict__ Cout,
                                                   const float* __restrict__ bgp) {
    const __half* A = (MODE == 3) ? d_yh : d_xh;

    extern __shared__ __half sm[];
    const uint32_t base = smem_u32(sm);

    const int tid  = threadIdx.x;
    const int bm = blockIdx.y * 128;
    const int bn = blockIdx.x * 128;
    const int wsel = bn >> 10;              // 0..3 for QKV+gate, 0 for MODE3
    const int bnl  = bn & 1023;

    const int warp = tid >> 5;
    const int lane = tid & 31;
    const int g   = lane >> 2;
    const int tig = lane & 3;
    const int warp_m = (warp & 1) * 64;
    const int warp_n = (warp >> 1) * 64;

    // ldmatrix per-thread bases (swizzled layout: row*128 + (colb ^ ((row&7)<<4)))
    const int sub = lane >> 3;
    const int r8  = lane & 7;
    const int row_a = warp_m + (sub & 1) * 8 + r8;
    const uint32_t coffA = (sub >> 1) * 16;
    const uint32_t aBase = (uint32_t)row_a * 128;
    const uint32_t swA   = (uint32_t)(row_a & 7) << 4;
    const int row_b = warp_n + (sub >> 1) * 8 + r8;
    const uint32_t coffB = (sub & 1) * 16;
    const uint32_t bBase = (uint32_t)row_b * 128;
    const uint32_t swB   = (uint32_t)(row_b & 7) << 4;

    const __half* ga = A + (size_t)bm * DMODEL;
    const __half* gb = W + ((size_t)wsel * DMODEL + bnl) * DMODEL;

    // cp.async mapping: 1024 16B-chunks per matrix, 8 per thread
    int rowc[8], cgc[8];
#pragma unroll
    for (int i = 0; i < 8; i++) {
        const int c = tid + i * 128;
        rowc[i] = c >> 3;
        cgc[i]  = c & 7;
    }

    float acc[4][8][4];
#pragma unroll
    for (int mt = 0; mt < 4; mt++)
#pragma unroll
        for (int nt = 0; nt < 8; nt++)
#pragma unroll
            for (int e = 0; e < 4; e++) acc[mt][nt][e] = 0.0f;

    auto issue = [&](int kt, int st) {
        const uint32_t sa = base + st * STAGE_B;
        const uint32_t sb = sa + TILEB;
#pragma unroll
        for (int i = 0; i < 8; i++) {
            const uint32_t d = (uint32_t)rowc[i] * 128 +
                               (((uint32_t)cgc[i] * 16) ^ (((uint32_t)rowc[i] & 7) << 4));
            const size_t s = (size_t)rowc[i] * DMODEL + kt * BKH + cgc[i] * 8;
            CPA16(sa + d, ga + s);
            CPA16(sb + d, gb + s);
        }
        asm volatile("cp.async.commit_group;" ::: "memory");
    };

    issue(0, 0);
    issue(1, 1);

    const int NT = DMODEL / BKH;    // 16
    int st = 0;
    for (int kt = 0; kt < NT; kt++) {
        if (kt < NT - 2) { asm volatile("cp.async.wait_group 1;" ::: "memory"); }
        else             { asm volatile("cp.async.wait_group 0;" ::: "memory"); }
        __syncthreads();   // stage kt ready; everyone done with stage kt-1

        if (kt + 2 < NT) {
            int s2 = st + 2; if (s2 >= NSTG) s2 -= NSTG;
            issue(kt + 2, s2);   // targets stage computed at kt-1: safe post-barrier
        }

        const uint32_t Ab = base + st * STAGE_B;
        const uint32_t Bb = Ab + TILEB;
#pragma unroll
        for (int k16b = 0; k16b < 128; k16b += 32) {   // 4 x k16 (bytes)
            unsigned af[4][4], bf[8][2];
#pragma unroll
            for (int mt = 0; mt < 4; mt++)
                LDSM4(af[mt][0], af[mt][1], af[mt][2], af[mt][3],
                      Ab + aBase + mt * 2048 + (((uint32_t)k16b + coffA) ^ swA));
#pragma unroll
            for (int p = 0; p < 4; p++)
                LDSM4(bf[2 * p][0], bf[2 * p][1], bf[2 * p + 1][0], bf[2 * p + 1][1],
                      Bb + bBase + p * 2048 + (((uint32_t)k16b + coffB) ^ swB));
#pragma unroll
            for (int mt = 0; mt < 4; mt++)
#pragma unroll
                for (int nt = 0; nt < 8; nt++) {
                    asm volatile(
                        "mma.sync.aligned.m16n8k16.row.col.f32.f16.f16.f32 "
                        "{%0,%1,%2,%3}, {%4,%5,%6,%7}, {%8,%9}, {%0,%1,%2,%3};"
                        : "+f"(acc[mt][nt][0]), "+f"(acc[mt][nt][1]),
                          "+f"(acc[mt][nt][2]), "+f"(acc[mt][nt][3])
                        : "r"(af[mt][0]), "r"(af[mt][1]), "r"(af[mt][2]), "r"(af[mt][3]),
                          "r"(bf[nt][0]), "r"(bf[nt][1]));
                }
        }
        if (++st >= NSTG) st -= NSTG;
    }

    // epilogue: paired stores (n pairs 2*tig, 2*tig+1)
#pragma unroll
    for (int mt = 0; mt < 4; mt++) {
#pragma unroll
        for (int nt = 0; nt < 8; nt++) {
#pragma unroll
            for (int ep = 0; ep < 2; ep++) {     // e pair: rows g / g+8
                const int m = bm + warp_m + mt * 16 + g + ep * 8;
                float c0 = acc[mt][nt][2 * ep + 0];
                float c1 = acc[mt][nt][2 * ep + 1];
                if (MODE == 3) {
                    const int n = bn + warp_n + nt * 8 + 2 * tig;
                    *(float2*)(Cout + (size_t)m * DMODEL + n) = make_float2(c0, c1);
                } else {
                    const int nl = bnl + warp_n + nt * 8 + 2 * tig;
                    const int b = m >> 11;
                    const int t = m & 2047;
                    if (wsel == 3) {
                        if (nl < NHEADS) {     // gate columns
                            float g0 = 1.0f / (1.0f + __expf(-(c0 + bgp[nl])));
                            float g1 = 1.0f / (1.0f + __expf(-(c1 + bgp[nl + 1])));
                            d_gbuf[(size_t)(b * NHEADS + nl) * SEQ + t]     = g0;
                            d_gbuf[(size_t)(b * NHEADS + nl + 1) * SEQ + t] = g1;
                        }
                    } else {
                        const int h = nl >> 6;
                        const int d = nl & 63;
                        const size_t idx = ((size_t)(b * NHEADS + h) * SEQ + t) * DHEAD + d;
                        __half2 hv;
                        if (wsel == 0) {
                            hv = __floats2half2_rn(phi(c0 * QSCALE), phi(c1 * QSCALE));
                            *(__half2*)(d_qh2 + idx) = hv;
                        } else if (wsel == 1) {
                            hv = __floats2half2_rn(phi(c0), phi(c1));
                            *(__half2*)(d_kh2 + idx) = hv;
                        } else {
                            hv = __floats2half2_rn(c0, c1);
                            *(__half2*)(d_vh2 + idx) = hv;
                        }
                    }
                }
            }
        }
    }
}

// ---------------- prep: pure streaming fp32->fp16 conversions ----------------
// blocks [0,8192):        x  (1 float4 per thread)
// blocks [8192,12288):    Wq,Wk,Wv,Wo -> slots 0,1,2,4
// blocks [12288,12352):   gate slot 3: rows 0-15 = Wg, rows 16-127 = 0
#define XB 8192
#define WB 4096
#define GB 64

__global__ __launch_bounds__(256) void prep_kernel(const float* __restrict__ x,
                                                   const float* __restrict__ wq,
                                                   const float* __restrict__ wk,
                                                   const float* __restrict__ wv,
                                                   const float* __restrict__ wo,
                                                   const float* __restrict__ Wg) {
    const int blk = blockIdx.x;
    const int tid = threadIdx.x;
    if (blk < XB) {
        const int i = blk * 256 + tid;
        const float4 v = ((const float4*)x)[i];
        __half2 h0 = __floats2half2_rn(v.x, v.y);
        __half2 h1 = __floats2half2_rn(v.z, v.w);
        uint2 u;
        u.x = *(unsigned*)&h0;
        u.y = *(unsigned*)&h1;
        *(uint2*)(d_xh + (size_t)i * 4) = u;
    } else if (blk < XB + WB) {
        const int j = blk - XB;
        const int w = j >> 10;
        const int slot = (w == 3) ? 4 : w;
        const int off = ((j & 1023) << 8) + tid;
        const float* src = (w == 0) ? wq : (w == 1) ? wk : (w == 2) ? wv : wo;
        const float4 v = ((const float4*)src)[off];
        __half2 h0 = __floats2half2_rn(v.x, v.y);
        __half2 h1 = __floats2half2_rn(v.z, v.w);
        uint2 u;
        u.x = *(unsigned*)&h0;
        u.y = *(unsigned*)&h1;
        *(uint2*)(d_wh + (size_t)slot * DMODEL * DMODEL + (size_t)off * 4) = u;
    } else {
        const int idx = (blk - XB - WB) * 256 + tid;   // 0..16383
        const int halfoff = idx * 8;
        const int row = halfoff >> 10;
        const int col = halfoff & 1023;
        __half2 h[4];
        if (row < NHEADS) {
            const float4 v0 = *(const float4*)(Wg + (size_t)row * DMODEL + col);
            const float4 v1 = *(const float4*)(Wg + (size_t)row * DMODEL + col + 4);
            h[0] = __floats2half2_rn(v0.x, v0.y);
            h[1] = __floats2half2_rn(v0.z, v0.w);
            h[2] = __floats2half2_rn(v1.x, v1.y);
            h[3] = __floats2half2_rn(v1.z, v1.w);
        } else {
            h[0] = h[1] = h[2] = h[3] = __floats2half2_rn(0.0f, 0.0f);
        }
        uint4 u;
        u.x = *(unsigned*)&h[0];
        u.y = *(unsigned*)&h[1];
        u.z = *(unsigned*)&h[2];
        u.w = *(unsigned*)&h[3];
        *(uint4*)(d_wh + (size_t)3 * DMODEL * DMODEL + halfoff) = u;
    }
}

// ---------------- gated scan: cp.async pipeline + warp-local f32 staging ----
// Block = (bh, jhalf): 32 state columns. Warp w owns rows [8w, 8w+8).
#define SS   8
#define NBUF 4
#define NSS  (SEQ / SS)            // 256 supersteps

__global__ __launch_bounds__(256) void scan_kernel() {
    const int blk  = blockIdx.x;           // 0..127
    const int bh   = blk >> 1;
    const int joff = (blk & 1) * 32;
    const int tid  = threadIdx.x;
    const int w    = tid >> 5;
    const int lane = tid & 31;

    __shared__ __half ksh[NBUF][SS][64];   // 4 KB
    __shared__ __half qsh[NBUF][SS][64];   // 4 KB
    __shared__ __half vsh[NBUF][SS][32];   // 2 KB
    __shared__ float  gsh[NBUF][SS];       // 128 B
    __shared__ float  kst[8][SS][8];       // 2 KB warp-private fp32 staging
    __shared__ float  qst[8][SS][8];       // 2 KB
    __shared__ float  ypart[SS][8][32];    // 4 KB

    const __half* kb = d_kh2 + (size_t)bh * SEQ * DHEAD;
    const __half* qb = d_qh2 + (size_t)bh * SEQ * DHEAD;
    const __half* vb = d_vh2 + (size_t)bh * SEQ * DHEAD;
    const float*  gb = d_gbuf + (size_t)bh * SEQ;

    const int b = bh >> 4;
    const int h = bh & 15;
    __half* yout = d_yh + (size_t)(b * SEQ) * DMODEL + h * DHEAD + joff + lane;

    const uint32_t k_s = smem_u32(&ksh[0][0][0]);
    const uint32_t q_s = smem_u32(&qsh[0][0][0]);
    const uint32_t v_s = smem_u32(&vsh[0][0][0]);
    const uint32_t g_s = smem_u32(&gsh[0][0]);

    float S[8];
#pragma unroll
    for (int ii = 0; ii < 8; ii++) S[ii] = 0.0f;

    // cp.async assignment (every thread commits every issue call)
    auto issue = [&](int t1, int buf) {
        if (tid < 64) {
            const int step = tid >> 3, c = tid & 7;
            CPA16(k_s + (uint32_t)(((buf * SS + step) * 64 + c * 8) * 2),
                  kb + (size_t)(t1 + step) * DHEAD + c * 8);
        } else if (tid < 128) {
            const int t2 = tid - 64;
            const int step = t2 >> 3, c = t2 & 7;
            CPA16(q_s + (uint32_t)(((buf * SS + step) * 64 + c * 8) * 2),
                  qb + (size_t)(t1 + step) * DHEAD + c * 8);
        } else if (tid < 160) {
            const int t3 = tid - 128;
            const int step = t3 >> 2, c = t3 & 3;
            CPA16(v_s + (uint32_t)(((buf * SS + step) * 32 + c * 8) * 2),
                  vb + (size_t)(t1 + step) * DHEAD + joff + c * 8);
        } else if (tid < 162) {
            const int s0 = (tid - 160) * 4;
            CPA16(g_s + (uint32_t)((buf * SS + s0) * 4), gb + t1 + s0);
        }
        asm volatile("cp.async.commit_group;" ::: "memory");
    };

    issue(0 * SS, 0);
    issue(1 * SS, 1);
    issue(2 * SS, 2);

    for (int ss = 0; ss < NSS; ss++) {
        const int buf = ss & 3;
        if (ss < NSS - 2) { asm volatile("cp.async.wait_group 2;" ::: "memory"); }
        else              { asm volatile("cp.async.wait_group 0;" ::: "memory"); }
        __syncthreads();   // buf data visible; all threads done with ss-1

        if (ss + 3 < NSS) issue((ss + 3) * SS, (ss + 3) & 3);

        // warp-local fp16 -> fp32 pre-convert of this warp's k/q rows
        {
            const __half2* kh2 = (const __half2*)&ksh[buf][0][0];  // [SS][32]
            const __half2* qh2 = (const __half2*)&qsh[buf][0][0];
            const int s = lane >> 2, p = lane & 3;
            const int src = s * 32 + 4 * w + p;
            float2 kf = __half22float2(kh2[src]);
            float2 qf = __half22float2(qh2[src]);
            *(float2*)&kst[w][s][2 * p] = kf;
            *(float2*)&qst[w][s][2 * p] = qf;
            __syncwarp();
        }

#pragma unroll
        for (int s = 0; s < SS; s++) {
            const float gt = gsh[buf][s];
            const float4 k0 = *(const float4*)&kst[w][s][0];
            const float4 k1 = *(const float4*)&kst[w][s][4];
            const float4 q0 = *(const float4*)&qst[w][s][0];
            const float4 q1 = *(const float4*)&qst[w][s][4];
            const float vj = __half2float(vsh[buf][s][lane]);
            float acc;
            S[0] = fmaf(k0.x, vj, gt * S[0]); acc = q0.x * S[0];
            S[1] = fmaf(k0.y, vj, gt * S[1]); acc = fmaf(q0.y, S[1], acc);
            S[2] = fmaf(k0.z, vj, gt * S[2]); acc = fmaf(q0.z, S[2], acc);
            S[3] = fmaf(k0.w, vj, gt * S[3]); acc = fmaf(q0.w, S[3], acc);
            S[4] = fmaf(k1.x, vj, gt * S[4]); acc = fmaf(q1.x, S[4], acc);
            S[5] = fmaf(k1.y, vj, gt * S[5]); acc = fmaf(q1.y, S[5], acc);
            S[6] = fmaf(k1.z, vj, gt * S[6]); acc = fmaf(q1.z, S[6], acc);
            S[7] = fmaf(k1.w, vj, gt * S[7]); acc = fmaf(q1.w, S[7], acc);
            ypart[s][w][lane] = acc;
        }
        __syncthreads();   // ypart complete

        {
            const int s = tid >> 5;
            float yv = ypart[s][0][lane] + ypart[s][1][lane]
                     + ypart[s][2][lane] + ypart[s][3][lane]
                     + ypart[s][4][lane] + ypart[s][5][lane]
                     + ypart[s][6][lane] + ypart[s][7][lane];
            yout[(size_t)(ss * SS + s) * DMODEL] = __float2half_rn(yv);
        }
    }
}

// ---------------- launch ----------------------------------------------------
extern "C" void kernel_launch(void* const* d_in, const int* in_sizes, int n_in,
                              void* d_out, int out_size) {
    const float* x  = (const float*)d_in[0];
    const float* Wq = (const float*)d_in[1];
    const float* Wk = (const float*)d_in[2];
    const float* Wv = (const float*)d_in[3];
    const float* Wo = (const float*)d_in[4];
    const float* Wg = (const float*)d_in[5];
    const float* bg = (const float*)d_in[6];
    float* out = (float*)d_out;

    cudaFuncSetAttribute(mma_gemm<0>, cudaFuncAttributeMaxDynamicSharedMemorySize, GEMM_SMEM);
    cudaFuncSetAttribute(mma_gemm<3>, cudaFuncAttributeMaxDynamicSharedMemorySize, GEMM_SMEM);

    void* p = nullptr;
    cudaGetSymbolAddress(&p, d_wh);
    __half* wh_base = (__half*)p;

    prep_kernel<<<XB + WB + GB, 256>>>(x, Wq, Wk, Wv, Wo, Wg);

    dim3 gqkv(25, MROWS / 128);                 // (25, 64): QKV + gate tile
    mma_gemm<0><<<gqkv, 128, GEMM_SMEM>>>(wh_base, nullptr, bg);

    scan_kernel<<<NBH * 2, 256>>>();

    dim3 go(DMODEL / 128, MROWS / 128);         // (8, 64)
    mma_gemm<3><<<go, 128, GEMM_SMEM>>>(wh_base + 4 * (size_t)DMODEL * DMODEL, out, nullptr);
}